// round 8
// baseline (speedup 1.0000x reference)
#include <cuda_runtime.h>
#include <math.h>
#include <stdint.h>

#define NC 65
#define NG 22
#define MAXB 64
#define EPS 1e-8f
#define TILE 128
#define THR_A 128

// ---- constants derived from AA64 = 'FFLLSSSSYY**CC*WLLLLPPPPHHQQRRRRIIIMTTTTNNKKSSRRVVVVAAAADDEEGGGG'
__constant__ int c_gid[NC] = {
    0,
    6,6, 11,11, 17,17,17,17, 21,21, 1,1, 3,3, 1, 20,
    11,11,11,11, 14,14,14,14, 8,8, 15,15, 16,16,16,16,
    9,9,9, 12, 18,18,18,18, 13,13, 10,10, 17,17, 16,16,
    19,19,19,19, 2,2,2,2, 4,4, 5,5, 7,7,7,7};
__constant__ float c_nsyn[NC] = {
    0.f,
    2,2, 6,6, 6,6,6,6, 2,2, 3,3, 2,2, 3, 1,
    6,6,6,6, 4,4,4,4, 2,2, 2,2, 6,6,6,6,
    3,3,3, 1, 4,4,4,4, 2,2, 2,2, 6,6, 6,6,
    4,4,4,4, 4,4,4,4, 2,2, 2,2, 4,4,4,4};

// ---- global scratch (zero-initialized at load; re-zeroed at end of every run)
__device__ double g_lwp[MAXB], g_lwt[MAXB];
__device__ double g_gcs[MAXB], g_pps[MAXB];
__device__ int    g_maskc[MAXB];
__device__ int    g_cntp[MAXB][NC], g_cntt[MAXB][NC];
__device__ int    g_obsp[MAXB][NC], g_obst[MAXB][NC];
__device__ double g_ce_sum;
__device__ int    g_ce_cnt;
__device__ double g_rscu, g_cai, g_gc, g_dyn, g_str;
__device__ int    g_bdone[MAXB];
__device__ int    g_fin;

// ------------- Single fused kernel -------------
__global__ void __launch_bounds__(THR_A) fusedK(
    const float* __restrict__ logits, const float* __restrict__ wmat,
    const float* __restrict__ refd,
    const float* __restrict__ gc,     const float* __restrict__ pause,
    const float* __restrict__ mfe,
    const int* __restrict__ tgt,      const int* __restrict__ aa,
    const int* __restrict__ species,  const unsigned char* __restrict__ mask,
    float* __restrict__ out, int L, int B)
{
    int b   = blockIdx.y;
    int l0  = blockIdx.x * TILE;
    int tid = threadIdx.x;
    int wid = tid >> 5, lane = tid & 31;
    int nblk = gridDim.x;

    extern __shared__ float smem[];
    float* s_tile = smem;                // TILE*NC floats, global layout (no pad)
    float* s_logw = smem + TILE * NC;    // NC floats

    __shared__ int   s_cntp[NC], s_cntt[NC], s_obsp[NC], s_obst[NC];
    __shared__ float r_ce[4], r_lwp[4], r_lwt[4];
    __shared__ int   r_cec[4], r_mk[4];
    __shared__ float r_gc, r_pp;

    if (tid < NC) {
        int sp = species[b];
        s_logw[tid] = __logf(fmaxf(wmat[sp * NC + tid], EPS));
        s_cntp[tid] = 0; s_cntt[tid] = 0; s_obsp[tid] = 0; s_obst[tid] = 0;
    }

    // Stage tile: pure float4 copy, identical layout to global
    {
        const float4* g4 = (const float4*)(logits + ((size_t)b * L + l0) * NC);
        float4* s4 = (float4*)s_tile;
        #pragma unroll 4
        for (int v = tid; v < TILE * NC / 4; v += THR_A) s4[v] = g4[v];
    }

    // gc / pause segment sums (warp 0 covers TILE floats of each)
    if (wid == 0) {
        const float4* gp = (const float4*)(gc    + (size_t)b * L + l0);
        const float4* pp = (const float4*)(pause + (size_t)b * L + l0);
        float4 x = gp[lane], y = pp[lane];
        float sg = x.x + x.y + x.z + x.w;
        float sp = y.x + y.y + y.z + y.w;
        #pragma unroll
        for (int o = 16; o; o >>= 1) {
            sg += __shfl_xor_sync(0xffffffffu, sg, o);
            sp += __shfl_xor_sync(0xffffffffu, sp, o);
        }
        if (lane == 0) { r_gc = sg; r_pp = sp; }
    }

    size_t gi = (size_t)b * L + l0 + tid;
    int t  = tgt[gi];
    int a  = aa[gi];
    int mk = mask[gi];

    __syncthreads();

    // One thread per row; stride-65 scalar LDS is bank-conflict-free
    const float* row = s_tile + tid * NC;

    float mx = row[0]; int am = 0;
    #pragma unroll
    for (int c = 1; c < NC; ++c) {
        float v = row[c];
        if (v > mx) { mx = v; am = c; }   // strict > => first index (jnp.argmax)
    }
    float ssum = 0.f;
    #pragma unroll
    for (int c = 0; c < NC; ++c) ssum += __expf(row[c] - mx);

    float nll = mx + __logf(ssum) - row[t];

    float ce  = (t != 0) ? nll : 0.f;
    float lwp = 0.f, lwt = 0.f;
    if (mk) {
        lwp = s_logw[am];
        lwt = s_logw[t];
        if (am > 0) { atomicAdd(&s_cntp[am], 1); if (a > 2) s_obsp[am] = 1; }
        if (t  > 0) { atomicAdd(&s_cntt[t], 1);  if (a > 2) s_obst[t]  = 1; }
    }
    #pragma unroll
    for (int o = 16; o; o >>= 1) {
        ce  += __shfl_xor_sync(0xffffffffu, ce,  o);
        lwp += __shfl_xor_sync(0xffffffffu, lwp, o);
        lwt += __shfl_xor_sync(0xffffffffu, lwt, o);
    }
    int cecw = __popc(__ballot_sync(0xffffffffu, t != 0));
    int mkw  = __popc(__ballot_sync(0xffffffffu, mk != 0));
    if (lane == 0) { r_ce[wid] = ce; r_lwp[wid] = lwp; r_lwt[wid] = lwt; r_cec[wid] = cecw; r_mk[wid] = mkw; }
    __syncthreads();

    if (tid < NC) {
        int cp = s_cntp[tid], ct = s_cntt[tid];
        if (cp) atomicAdd(&g_cntp[b][tid], cp);
        if (ct) atomicAdd(&g_cntt[b][tid], ct);
        if (s_obsp[tid]) g_obsp[b][tid] = 1;   // idempotent
        if (s_obst[tid]) g_obst[b][tid] = 1;
    }
    if (tid == 0) {
        float ceS  = r_ce[0]  + r_ce[1]  + r_ce[2]  + r_ce[3];
        float lwpS = r_lwp[0] + r_lwp[1] + r_lwp[2] + r_lwp[3];
        float lwtS = r_lwt[0] + r_lwt[1] + r_lwt[2] + r_lwt[3];
        int   cecS = r_cec[0] + r_cec[1] + r_cec[2] + r_cec[3];
        int   mkS  = r_mk[0]  + r_mk[1]  + r_mk[2]  + r_mk[3];
        atomicAdd(&g_ce_sum, (double)ceS);
        atomicAdd(&g_ce_cnt, cecS);
        atomicAdd(&g_lwp[b], (double)lwpS);
        atomicAdd(&g_lwt[b], (double)lwtS);
        atomicAdd(&g_maskc[b], mkS);
        atomicAdd(&g_gcs[b], (double)r_gc);
        atomicAdd(&g_pps[b], (double)r_pp);
    }

    // ---------- per-batch completion ticket ----------
    __threadfence();                       // release our accumulations
    __shared__ int s_rank;
    if (tid == 0) s_rank = atomicAdd(&g_bdone[b], 1);
    __syncthreads();
    if (s_rank != nblk - 1) return;        // uniform branch (smem-broadcast)

    // ========== per-batch epilogue (last block of this b) ==========
    __threadfence();                       // acquire other blocks' writes

    __shared__ float e_gsp[NG], e_gst[NG];
    __shared__ float e_sp, e_st;
    __shared__ double e_kl;
    if (tid < NG) { e_gsp[tid] = 0.f; e_gst[tid] = 0.f; }
    if (tid == 0) { e_sp = 0.f; e_st = 0.f; e_kl = 0.0; }
    __syncthreads();

    int gid = 0, op = 0, ot = 0;
    float ocp = 0.f, oct = 0.f;
    if (tid < NC) {
        gid = c_gid[tid];
        bool coding = (tid != 0) && (tid != 11) && (tid != 12) && (tid != 15);
        op = g_obsp[b][tid] && coding;
        ot = g_obst[b][tid] && coding;
        ocp = op ? (float)g_cntp[b][tid] : 0.f;
        oct = ot ? (float)g_cntt[b][tid] : 0.f;
        atomicAdd(&e_gsp[gid], ocp);
        atomicAdd(&e_gst[gid], oct);
    }
    __syncthreads();

    float pterm = 0.f, tterm = 0.f;
    if (tid < NC) {
        float totp = e_gsp[gid], tott = e_gst[gid];
        float ns = c_nsyn[tid];
        float rp = (op && totp > 0.f) ? ocp * ns / fmaxf(totp, 1.f) : 0.f;
        float rt = (ot && tott > 0.f) ? oct * ns / fmaxf(tott, 1.f) : 0.f;
        pterm = rp + EPS;
        int sp = species[b];
        tterm = 0.7f * rt + 0.3f * refd[sp * NC + tid] + EPS;
        atomicAdd(&e_sp, pterm);
        atomicAdd(&e_st, tterm);
    }
    __syncthreads();

    if (tid < NC) {
        double tt = (double)tterm / (double)e_st;
        double pp = (double)pterm / (double)e_sp;
        atomicAdd(&e_kl, tt * (log(tt) - log(pp)));
    }
    __syncthreads();

    if (tid == 0) {
        atomicAdd(&g_rscu, e_kl);
        double denom = fmax((double)g_maskc[b], 1.0);
        double pc = exp(g_lwp[b] / denom);
        double tc = exp(g_lwt[b] / denom);
        atomicAdd(&g_cai, fmax(tc - pc, 0.0));
        double gm = g_gcs[b] / (double)L - 0.5;
        double pm = g_pps[b] / (double)L - 0.1;
        double sd = (double)mfe[b] + 20.0;
        atomicAdd(&g_gc,  gm * gm);
        atomicAdd(&g_dyn, pm * pm);
        atomicAdd(&g_str, sd * sd);
    }

    // ---------- global completion ticket ----------
    __threadfence();
    __shared__ int s_f;
    if (tid == 0) s_f = atomicAdd(&g_fin, 1);
    __syncthreads();
    if (s_f != B - 1) return;

    // ========== final combine (very last epilogue block) ==========
    __threadfence();
    if (tid == 0) {
        double invB = 1.0 / (double)B;
        double cev = g_ce_sum / fmax((double)g_ce_cnt, 1.0);
        out[0] = (float)(cev
                       + 0.4  * g_cai  * invB
                       + 0.3  * g_rscu * invB
                       + 0.1  * g_gc   * invB
                       + 0.15 * g_str  * invB
                       + 0.1  * g_dyn  * invB);
    }
    __syncthreads();   // combine reads done before zeroing

    // re-zero all scratch for the next (graph-replayed) run
    for (int i = tid; i < MAXB * NC; i += THR_A) {
        ((int*)g_cntp)[i] = 0; ((int*)g_cntt)[i] = 0;
        ((int*)g_obsp)[i] = 0; ((int*)g_obst)[i] = 0;
    }
    for (int i = tid; i < MAXB; i += THR_A) {
        g_lwp[i] = 0.0; g_lwt[i] = 0.0;
        g_gcs[i] = 0.0; g_pps[i] = 0.0;
        g_maskc[i] = 0; g_bdone[i] = 0;
    }
    if (tid == 0) {
        g_ce_sum = 0.0; g_ce_cnt = 0;
        g_rscu = 0.0; g_cai = 0.0; g_gc = 0.0; g_dyn = 0.0; g_str = 0.0;
        g_fin = 0;
    }
}

extern "C" void kernel_launch(void* const* d_in, const int* in_sizes, int n_in,
                              void* d_out, int out_size)
{
    const float* logits  = (const float*)d_in[0];
    const float* wmat    = (const float*)d_in[1];
    const float* refd    = (const float*)d_in[2];
    const float* gc      = (const float*)d_in[3];
    const float* mfe     = (const float*)d_in[4];
    const float* pause   = (const float*)d_in[5];
    const int*   tgt     = (const int*)d_in[6];
    const int*   aa      = (const int*)d_in[7];
    const int*   species = (const int*)d_in[8];
    const unsigned char* mask = (const unsigned char*)d_in[9];

    int B = in_sizes[4];             // mfe has B elements
    int L = in_sizes[3] / B;         // gc_pred has B*L elements

    dim3 grid(L / TILE, B);
    size_t smemA = (TILE * NC + NC) * sizeof(float);
    fusedK<<<grid, THR_A, smemA>>>(logits, wmat, refd, gc, pause, mfe,
                                   tgt, aa, species, mask,
                                   (float*)d_out, L, B);
}